// round 1
// baseline (speedup 1.0000x reference)
#include <cuda_runtime.h>
#include <cuda_bf16.h>

// Problem constants
#define BB   2
#define TT   2048
#define DD   2048
#define HH   32
#define GG   8
#define REPF 4
#define HDIM 64
#define KVD  (GG * HDIM)   // 512

// Scratch (allocation-free rule: __device__ globals)
__device__ float g_q  [(size_t)BB * TT * DD];
__device__ float g_k  [(size_t)BB * TT * KVD];
__device__ float g_v  [(size_t)BB * TT * KVD];
__device__ float g_att[(size_t)BB * TT * DD];

// ---------------------------------------------------------------------------
// Classic 128x128x8 fp32 SGEMM, 256 threads, 8x8 per-thread microtile.
// Dims assumed divisible by tile sizes (4096 x {2048,512} x 2048 all are).
// ---------------------------------------------------------------------------
__global__ __launch_bounds__(256) void sgemm128(
    const float* __restrict__ A, const float* __restrict__ B,
    float* __restrict__ C, int M, int N, int K)
{
    const int BM = 128, BN = 128, BK = 8, TM = 8, TN = 8;
    __shared__ float As[BK][BM];
    __shared__ float Bs[BK][BN];

    int tid = threadIdx.x;
    int bn0 = blockIdx.x * BN;
    int bm0 = blockIdx.y * BM;
    int tx = tid & 15;       // 16 cols of threads
    int ty = tid >> 4;       // 16 rows of threads

    // A tile load mapping: 128 rows x 8 cols, float4 per thread
    int arow = tid >> 1;
    int acol = (tid & 1) * 4;
    // B tile load mapping: 8 rows x 128 cols, float4 per thread
    int brow = tid >> 5;
    int bcol = (tid & 31) * 4;

    float acc[TM][TN];
    #pragma unroll
    for (int i = 0; i < TM; i++)
        #pragma unroll
        for (int j = 0; j < TN; j++) acc[i][j] = 0.f;

    for (int k0 = 0; k0 < K; k0 += BK) {
        float4 a4 = *(const float4*)&A[(size_t)(bm0 + arow) * K + k0 + acol];
        As[acol + 0][arow] = a4.x;
        As[acol + 1][arow] = a4.y;
        As[acol + 2][arow] = a4.z;
        As[acol + 3][arow] = a4.w;
        float4 b4 = *(const float4*)&B[(size_t)(k0 + brow) * N + bn0 + bcol];
        *(float4*)&Bs[brow][bcol] = b4;
        __syncthreads();

        #pragma unroll
        for (int kk = 0; kk < BK; kk++) {
            float rm[TM], rn[TN];
            #pragma unroll
            for (int i = 0; i < TM; i++) rm[i] = As[kk][ty * TM + i];
            #pragma unroll
            for (int j = 0; j < TN; j++) rn[j] = Bs[kk][tx * TN + j];
            #pragma unroll
            for (int i = 0; i < TM; i++)
                #pragma unroll
                for (int j = 0; j < TN; j++)
                    acc[i][j] += rm[i] * rn[j];
        }
        __syncthreads();
    }

    #pragma unroll
    for (int i = 0; i < TM; i++) {
        float* crow = &C[(size_t)(bm0 + ty * TM + i) * N + bn0 + tx * TN];
        #pragma unroll
        for (int j = 0; j < TN; j += 4) {
            float4 v4 = make_float4(acc[i][j], acc[i][j+1], acc[i][j+2], acc[i][j+3]);
            *(float4*)&crow[j] = v4;
        }
    }
}

// ---------------------------------------------------------------------------
// Flash-attention (fp32, causal, GQA). One CTA = 64 query rows of one head.
// Each thread owns one query row: Q row + O accumulator in registers.
// K/V tiles (64x64) staged in smem; scores staged in Ss[j][tid] (conflict-free).
// ---------------------------------------------------------------------------
__global__ __launch_bounds__(64) void flash_attn(
    const float* __restrict__ Q, const float* __restrict__ Kg,
    const float* __restrict__ Vg, float* __restrict__ O)
{
    const int BT = 64;
    int qt = blockIdx.x;           // q tile
    int h  = blockIdx.y;           // head
    int b  = blockIdx.z;           // batch
    int g  = h >> 2;               // kv group (REP = 4)
    int tid = threadIdx.x;
    int qrow = qt * BT + tid;

    const float scale = 0.125f;    // 1/sqrt(64)

    const float* qp = Q + ((size_t)(b * TT + qrow)) * DD + h * HDIM;
    float qr[HDIM];
    #pragma unroll
    for (int d = 0; d < HDIM; d++) qr[d] = qp[d] * scale;

    float o[HDIM];
    #pragma unroll
    for (int d = 0; d < HDIM; d++) o[d] = 0.f;
    float m = -1e30f, l = 0.f;

    __shared__ float Ks[BT][HDIM];
    __shared__ float Vs[BT][HDIM];
    __shared__ float Ss[BT][BT];   // [j][tid]

    const float* kbase = Kg + (size_t)b * TT * KVD + (size_t)g * HDIM;
    const float* vbase = Vg + (size_t)b * TT * KVD + (size_t)g * HDIM;

    for (int kt = 0; kt <= qt; kt++) {
        // Cooperative tile load: row i, col tid (coalesced 256B rows)
        #pragma unroll 4
        for (int i = 0; i < BT; i++) {
            size_t roff = (size_t)(kt * BT + i) * KVD + tid;
            Ks[i][tid] = kbase[roff];
            Vs[i][tid] = vbase[roff];
        }
        __syncthreads();

        // causal: key pos kt*64+j must be <= qrow; on diagonal tile j <= tid
        int jmax = (kt < qt) ? BT : (tid + 1);

        float tmax = m;
        for (int j = 0; j < jmax; j++) {
            float s = 0.f;
            #pragma unroll
            for (int d = 0; d < HDIM; d++) s += qr[d] * Ks[j][d];
            Ss[j][tid] = s;
            tmax = fmaxf(tmax, s);
        }
        float corr = __expf(m - tmax);
        l *= corr;
        #pragma unroll
        for (int d = 0; d < HDIM; d++) o[d] *= corr;
        m = tmax;

        for (int j = 0; j < jmax; j++) {
            float p = __expf(Ss[j][tid] - m);
            l += p;
            #pragma unroll
            for (int d = 0; d < HDIM; d++) o[d] += p * Vs[j][d];
        }
        __syncthreads();
    }

    float inv = 1.f / l;
    float* op = O + ((size_t)(b * TT + qrow)) * DD + h * HDIM;
    #pragma unroll
    for (int d = 0; d < HDIM; d++) op[d] = o[d] * inv;
}

// ---------------------------------------------------------------------------
extern "C" void kernel_launch(void* const* d_in, const int* in_sizes, int n_in,
                              void* d_out, int out_size)
{
    const float* x  = (const float*)d_in[0];
    const float* Wq = (const float*)d_in[1];
    const float* Wk = (const float*)d_in[2];
    const float* Wv = (const float*)d_in[3];
    const float* Wo = (const float*)d_in[4];
    float* out = (float*)d_out;

    float *q, *k, *v, *att;
    cudaGetSymbolAddress((void**)&q,   g_q);
    cudaGetSymbolAddress((void**)&k,   g_k);
    cudaGetSymbolAddress((void**)&v,   g_v);
    cudaGetSymbolAddress((void**)&att, g_att);

    const int M = BB * TT;  // 4096

    // Projections
    sgemm128<<<dim3(DD  / 128, M / 128), 256>>>(x, Wq, q, M, DD,  DD);
    sgemm128<<<dim3(KVD / 128, M / 128), 256>>>(x, Wk, k, M, KVD, DD);
    sgemm128<<<dim3(KVD / 128, M / 128), 256>>>(x, Wv, v, M, KVD, DD);

    // Attention
    flash_attn<<<dim3(TT / 64, HH, BB), 64>>>(q, k, v, att);

    // Output projection
    sgemm128<<<dim3(DD / 128, M / 128), 256>>>(att, Wo, out, M, DD, DD);
}

// round 3
// speedup vs baseline: 1.8586x; 1.8586x over previous
#include <cuda_runtime.h>
#include <cuda_bf16.h>
#include <cstdint>

// -------------------- problem constants --------------------
#define BB 2
#define TT 2048
#define DD 2048
#define HH 32
#define GG 8
#define HDIM 64
#define KVD 512            // G * HDIM
#define MM (BB*TT)         // 4096

// -------------------- device scratch (allocation-free rule) --------------------
__device__ float g_q  [(size_t)MM*DD];
__device__ float g_k  [(size_t)MM*KVD];
__device__ float g_v  [(size_t)MM*KVD];
__device__ float g_att[(size_t)MM*DD];

__device__ __nv_bfloat16 g_xh[(size_t)MM*DD],  g_xl[(size_t)MM*DD];
__device__ __nv_bfloat16 g_ah[(size_t)MM*DD],  g_al[(size_t)MM*DD];
// transposed weights: [N][K] (K contiguous) -> acts as col-major B for mma.row.col
__device__ __nv_bfloat16 g_wqh[(size_t)DD*DD],  g_wql[(size_t)DD*DD];
__device__ __nv_bfloat16 g_wkh[(size_t)KVD*DD], g_wkl[(size_t)KVD*DD];
__device__ __nv_bfloat16 g_wvh[(size_t)KVD*DD], g_wvl[(size_t)KVD*DD];
__device__ __nv_bfloat16 g_woh[(size_t)DD*DD],  g_wol[(size_t)DD*DD];

// -------------------- helpers (all plain sm_80+ features; no 'a'-only PTX) ----
__device__ __forceinline__ uint32_t smem_u32(const void* p) {
    uint32_t a;
    asm("{ .reg .u64 t; cvta.to.shared.u64 t, %1; cvt.u32.u64 %0, t; }" : "=r"(a) : "l"(p));
    return a;
}
__device__ __forceinline__ void cp16(uint32_t saddr, const void* g) {
    asm volatile("cp.async.cg.shared.global [%0], [%1], 16;" :: "r"(saddr), "l"(g));
}
#define CP_COMMIT() asm volatile("cp.async.commit_group;" ::: "memory")
#define CP_WAIT0()  asm volatile("cp.async.wait_group 0;" ::: "memory")

__device__ __forceinline__ void ldsm_x4(uint32_t& r0, uint32_t& r1, uint32_t& r2,
                                        uint32_t& r3, uint32_t addr) {
    asm volatile("ldmatrix.sync.aligned.m8n8.x4.shared.b16 {%0,%1,%2,%3}, [%4];"
                 : "=r"(r0), "=r"(r1), "=r"(r2), "=r"(r3) : "r"(addr));
}
__device__ __forceinline__ void mma16816(float* c, const uint32_t* a,
                                         uint32_t b0, uint32_t b1) {
    asm volatile("mma.sync.aligned.m16n8k16.row.col.f32.bf16.bf16.f32 "
                 "{%0,%1,%2,%3}, {%4,%5,%6,%7}, {%8,%9}, {%0,%1,%2,%3};"
                 : "+f"(c[0]), "+f"(c[1]), "+f"(c[2]), "+f"(c[3])
                 : "r"(a[0]), "r"(a[1]), "r"(a[2]), "r"(a[3]), "r"(b0), "r"(b1));
}

// smem tile layout: 128 rows x 32 bf16 (64B rows, 4x16B chunks),
// chunk swizzle: phys_chunk = c ^ ((row>>1)&3)  -> conflict-free stores + ldmatrix
__device__ __forceinline__ uint32_t sw_off(int row, int c) {
    return (uint32_t)(row * 64 + ((c ^ ((row >> 1) & 3)) << 4));
}

// -------------------- split / transpose prep kernels --------------------
__global__ void split_pair(const float* __restrict__ X, __nv_bfloat16* __restrict__ Xh,
                           __nv_bfloat16* __restrict__ Xl, int n4) {
    int i = blockIdx.x * blockDim.x + threadIdx.x;
    if (i >= n4) return;
    float4 v = ((const float4*)X)[i];
    __nv_bfloat16 h0 = __float2bfloat16_rn(v.x);
    __nv_bfloat16 h1 = __float2bfloat16_rn(v.y);
    __nv_bfloat16 h2 = __float2bfloat16_rn(v.z);
    __nv_bfloat16 h3 = __float2bfloat16_rn(v.w);
    ((__nv_bfloat162*)Xh)[2*i+0] = __nv_bfloat162(h0, h1);
    ((__nv_bfloat162*)Xh)[2*i+1] = __nv_bfloat162(h2, h3);
    ((__nv_bfloat162*)Xl)[2*i+0] = __nv_bfloat162(
        __float2bfloat16_rn(v.x - __bfloat162float(h0)),
        __float2bfloat16_rn(v.y - __bfloat162float(h1)));
    ((__nv_bfloat162*)Xl)[2*i+1] = __nv_bfloat162(
        __float2bfloat16_rn(v.z - __bfloat162float(h2)),
        __float2bfloat16_rn(v.w - __bfloat162float(h3)));
}

// W[K][N] fp32 -> Th/Tl[N][K] bf16 (transposed split)
__global__ void splitT(const float* __restrict__ W, __nv_bfloat16* __restrict__ Th,
                       __nv_bfloat16* __restrict__ Tl, int K, int N) {
    __shared__ float t[32][33];
    int n0 = blockIdx.x * 32, k0 = blockIdx.y * 32;
    int tx = threadIdx.x, ty = threadIdx.y;   // 32 x 8
    #pragma unroll
    for (int j = 0; j < 32; j += 8)
        t[ty + j][tx] = W[(size_t)(k0 + ty + j) * N + n0 + tx];
    __syncthreads();
    #pragma unroll
    for (int j = 0; j < 32; j += 8) {
        float v = t[tx][ty + j];
        __nv_bfloat16 h = __float2bfloat16_rn(v);
        size_t o = (size_t)(n0 + ty + j) * K + k0 + tx;
        Th[o] = h;
        Tl[o] = __float2bfloat16_rn(v - __bfloat162float(h));
    }
}

// -------------------- split-bf16 HMMA GEMM --------------------
// C[M][N] = Ah*Bh^T + Ah*Bl^T + Al*Bh^T   (A:[M][K] row-major, B:[N][K] K-contig)
// 256 threads, block 128x128, BK=32, warp tile 32x64, double-buffered cp.async.
#define TILE_B 8192                    // one 128x32 bf16 tile
#define BUF_B  (4 * TILE_B)            // Ah, Al, Bh, Bl
#define SMEM_GEMM (2 * BUF_B)          // double buffer = 64KB

__global__ __launch_bounds__(256) void gemm_mma(
    const __nv_bfloat16* __restrict__ Ah, const __nv_bfloat16* __restrict__ Al,
    const __nv_bfloat16* __restrict__ Bh, const __nv_bfloat16* __restrict__ Bl,
    float* __restrict__ C, int M, int N, int K)
{
    extern __shared__ char sm[];
    uint32_t sb = smem_u32(sm);
    int tid = threadIdx.x, lid = tid & 31, wid = tid >> 5;
    int wm = (wid & 3) * 32;           // warp m offset in block
    int wn = (wid >> 2) * 64;          // warp n offset
    int bm0 = blockIdx.y * 128, bn0 = blockIdx.x * 128;

    float c[2][8][4];
    #pragma unroll
    for (int i = 0; i < 2; i++)
        #pragma unroll
        for (int j = 0; j < 8; j++)
            #pragma unroll
            for (int q = 0; q < 4; q++) c[i][j][q] = 0.f;

    // per-thread load slots: 2 chunks per tile (512 chunks / 256 threads)
    int r0_ = tid >> 2, c0_ = tid & 3;
    int r1_ = (tid + 256) >> 2, c1_ = (tid + 256) & 3;
    uint32_t so0 = sw_off(r0_, c0_), so1 = sw_off(r1_, c1_);

    auto issue_load = [&](int buf, int k0) {
        uint32_t base = sb + buf * BUF_B;
        const __nv_bfloat16* a0 = Ah + (size_t)(bm0 + r0_) * K + k0 + c0_ * 8;
        const __nv_bfloat16* a1 = Ah + (size_t)(bm0 + r1_) * K + k0 + c1_ * 8;
        const __nv_bfloat16* b0 = Bh + (size_t)(bn0 + r0_) * K + k0 + c0_ * 8;
        const __nv_bfloat16* b1 = Bh + (size_t)(bn0 + r1_) * K + k0 + c1_ * 8;
        size_t dA = (size_t)(Al - Ah), dB = (size_t)(Bl - Bh);
        cp16(base + 0*TILE_B + so0, a0);      cp16(base + 0*TILE_B + so1, a1);
        cp16(base + 1*TILE_B + so0, a0 + dA); cp16(base + 1*TILE_B + so1, a1 + dA);
        cp16(base + 2*TILE_B + so0, b0);      cp16(base + 2*TILE_B + so1, b1);
        cp16(base + 3*TILE_B + so0, b0 + dB); cp16(base + 3*TILE_B + so1, b1 + dB);
        CP_COMMIT();
    };

    int NK = K / 32;
    issue_load(0, 0);

    for (int kt = 0; kt < NK; kt++) {
        CP_WAIT0();
        __syncthreads();
        if (kt + 1 < NK) issue_load((kt + 1) & 1, (kt + 1) * 32);

        uint32_t base = sb + (kt & 1) * BUF_B;
        #pragma unroll
        for (int ks = 0; ks < 2; ks++) {
            int kc = ks * 2;
            uint32_t ah[2][4], al[2][4], bh[4][4], bl[4][4];
            #pragma unroll
            for (int mt = 0; mt < 2; mt++) {
                int row = wm + mt * 16 + (lid & 15);
                int ch = kc + (lid >> 4);
                uint32_t off = sw_off(row, ch);
                ldsm_x4(ah[mt][0], ah[mt][1], ah[mt][2], ah[mt][3], base + 0*TILE_B + off);
                ldsm_x4(al[mt][0], al[mt][1], al[mt][2], al[mt][3], base + 1*TILE_B + off);
            }
            #pragma unroll
            for (int bt = 0; bt < 4; bt++) {
                int row = wn + bt * 16 + (lid & 7) + ((lid >> 4) << 3);
                int ch = kc + ((lid >> 3) & 1);
                uint32_t off = sw_off(row, ch);
                ldsm_x4(bh[bt][0], bh[bt][1], bh[bt][2], bh[bt][3], base + 2*TILE_B + off);
                ldsm_x4(bl[bt][0], bl[bt][1], bl[bt][2], bl[bt][3], base + 3*TILE_B + off);
            }
            #pragma unroll
            for (int mt = 0; mt < 2; mt++)
                #pragma unroll
                for (int bt = 0; bt < 4; bt++)
                    #pragma unroll
                    for (int hn = 0; hn < 2; hn++) {
                        float* cc = c[mt][bt * 2 + hn];
                        mma16816(cc, ah[mt], bh[bt][hn*2], bh[bt][hn*2+1]); // Ah*Bh
                        mma16816(cc, ah[mt], bl[bt][hn*2], bl[bt][hn*2+1]); // Ah*Bl
                        mma16816(cc, al[mt], bh[bt][hn*2], bh[bt][hn*2+1]); // Al*Bh
                    }
        }
        __syncthreads();
    }

    // epilogue
    #pragma unroll
    for (int mt = 0; mt < 2; mt++) {
        int row = bm0 + wm + mt * 16 + (lid >> 2);
        #pragma unroll
        for (int nt = 0; nt < 8; nt++) {
            int col = bn0 + wn + nt * 8 + (lid & 3) * 2;
            *(float2*)&C[(size_t)row * N + col]       = make_float2(c[mt][nt][0], c[mt][nt][1]);
            *(float2*)&C[(size_t)(row + 8) * N + col] = make_float2(c[mt][nt][2], c[mt][nt][3]);
        }
    }
}

// -------------------- flash attention (fp32, causal, GQA) --------------------
__global__ __launch_bounds__(64) void flash_attn(
    const float* __restrict__ Q, const float* __restrict__ Kg,
    const float* __restrict__ Vg, float* __restrict__ O)
{
    const int BT = 64;
    int qt = blockIdx.x, h = blockIdx.y, b = blockIdx.z;
    int g = h >> 2;
    int tid = threadIdx.x;
    int qrow = qt * BT + tid;

    __shared__ float4 Ks4[BT][16];
    __shared__ float4 Vs4[BT][16];
    __shared__ float  Ss[BT][BT];

    const float4* qp = (const float4*)(Q + ((size_t)(b * TT + qrow)) * DD + h * HDIM);
    float4 qr[16];
    #pragma unroll
    for (int i = 0; i < 16; i++) {
        float4 t = qp[i];
        t.x *= 0.125f; t.y *= 0.125f; t.z *= 0.125f; t.w *= 0.125f;
        qr[i] = t;
    }
    float4 o4[16];
    #pragma unroll
    for (int i = 0; i < 16; i++) o4[i] = make_float4(0.f, 0.f, 0.f, 0.f);
    float m = -1e30f, l = 0.f;

    const float* kb = Kg + (size_t)b * TT * KVD + g * HDIM;
    const float* vb = Vg + (size_t)b * TT * KVD + g * HDIM;

    for (int kt = 0; kt <= qt; kt++) {
        #pragma unroll 4
        for (int i = 0; i < 16; i++) {
            int idx = tid + 64 * i;
            int row = idx >> 4, c4 = idx & 15;
            size_t off = (size_t)(kt * BT + row) * KVD + c4 * 4;
            Ks4[row][c4] = *(const float4*)(kb + off);
            Vs4[row][c4] = *(const float4*)(vb + off);
        }
        __syncthreads();

        int jmax = (kt < qt) ? BT : (tid + 1);
        float tmax = m;
        for (int j = 0; j < jmax; j++) {
            float s = 0.f;
            #pragma unroll
            for (int i = 0; i < 16; i++) {
                float4 kk = Ks4[j][i];
                s += qr[i].x * kk.x; s += qr[i].y * kk.y;
                s += qr[i].z * kk.z; s += qr[i].w * kk.w;
            }
            Ss[j][tid] = s;
            tmax = fmaxf(tmax, s);
        }
        if (tmax > m) {
            float corr = __expf(m - tmax);
            l *= corr;
            #pragma unroll
            for (int i = 0; i < 16; i++) {
                o4[i].x *= corr; o4[i].y *= corr; o4[i].z *= corr; o4[i].w *= corr;
            }
            m = tmax;
        }
        for (int j = 0; j < jmax; j++) {
            float p = __expf(Ss[j][tid] - m);
            l += p;
            #pragma unroll
            for (int i = 0; i < 16; i++) {
                float4 vv = Vs4[j][i];
                o4[i].x += p * vv.x; o4[i].y += p * vv.y;
                o4[i].z += p * vv.z; o4[i].w += p * vv.w;
            }
        }
        __syncthreads();
    }
    float inv = 1.f / l;
    float4* op = (float4*)(O + ((size_t)(b * TT + qrow)) * DD + h * HDIM);
    #pragma unroll
    for (int i = 0; i < 16; i++) {
        float4 t = o4[i];
        t.x *= inv; t.y *= inv; t.z *= inv; t.w *= inv;
        op[i] = t;
    }
}

// -------------------- launch --------------------
extern "C" void kernel_launch(void* const* d_in, const int* in_sizes, int n_in,
                              void* d_out, int out_size)
{
    const float* x  = (const float*)d_in[0];
    const float* Wq = (const float*)d_in[1];
    const float* Wk = (const float*)d_in[2];
    const float* Wv = (const float*)d_in[3];
    const float* Wo = (const float*)d_in[4];
    float* out = (float*)d_out;

    float *q, *k, *v, *att;
    __nv_bfloat16 *xh, *xl, *ah, *al, *wqh, *wql, *wkh, *wkl, *wvh, *wvl, *woh, *wol;
    cudaGetSymbolAddress((void**)&q, g_q);     cudaGetSymbolAddress((void**)&k, g_k);
    cudaGetSymbolAddress((void**)&v, g_v);     cudaGetSymbolAddress((void**)&att, g_att);
    cudaGetSymbolAddress((void**)&xh, g_xh);   cudaGetSymbolAddress((void**)&xl, g_xl);
    cudaGetSymbolAddress((void**)&ah, g_ah);   cudaGetSymbolAddress((void**)&al, g_al);
    cudaGetSymbolAddress((void**)&wqh, g_wqh); cudaGetSymbolAddress((void**)&wql, g_wql);
    cudaGetSymbolAddress((void**)&wkh, g_wkh); cudaGetSymbolAddress((void**)&wkl, g_wkl);
    cudaGetSymbolAddress((void**)&wvh, g_wvh); cudaGetSymbolAddress((void**)&wvl, g_wvl);
    cudaGetSymbolAddress((void**)&woh, g_woh); cudaGetSymbolAddress((void**)&wol, g_wol);

    cudaFuncSetAttribute(gemm_mma, cudaFuncAttributeMaxDynamicSharedMemorySize, SMEM_GEMM);

    // prep: split x, split+transpose weights
    int n4 = MM * DD / 4;
    split_pair<<<(n4 + 255) / 256, 256>>>(x, xh, xl, n4);
    splitT<<<dim3(DD / 32,  DD / 32), dim3(32, 8)>>>(Wq, wqh, wql, DD, DD);
    splitT<<<dim3(KVD / 32, DD / 32), dim3(32, 8)>>>(Wk, wkh, wkl, DD, KVD);
    splitT<<<dim3(KVD / 32, DD / 32), dim3(32, 8)>>>(Wv, wvh, wvl, DD, KVD);
    splitT<<<dim3(DD / 32,  DD / 32), dim3(32, 8)>>>(Wo, woh, wol, DD, DD);

    // projections (HMMA split-bf16)
    gemm_mma<<<dim3(DD / 128,  MM / 128), 256, SMEM_GEMM>>>(xh, xl, wqh, wql, q, MM, DD,  DD);
    gemm_mma<<<dim3(KVD / 128, MM / 128), 256, SMEM_GEMM>>>(xh, xl, wkh, wkl, k, MM, KVD, DD);
    gemm_mma<<<dim3(KVD / 128, MM / 128), 256, SMEM_GEMM>>>(xh, xl, wvh, wvl, v, MM, KVD, DD);

    // attention
    flash_attn<<<dim3(TT / 64, HH, BB), 64>>>(q, k, v, att);

    // output projection
    split_pair<<<(n4 + 255) / 256, 256>>>(att, ah, al, n4);
    gemm_mma<<<dim3(DD / 128, MM / 128), 256, SMEM_GEMM>>>(ah, al, woh, wol, out, MM, DD, DD);
}

// round 4
// speedup vs baseline: 4.0244x; 2.1652x over previous
#include <cuda_runtime.h>
#include <cuda_bf16.h>
#include <cstdint>

// -------------------- problem constants --------------------
#define BB 2
#define TT 2048
#define DD 2048
#define HH 32
#define GG 8
#define HDIM 64
#define KVD 512            // G * HDIM
#define MM (BB*TT)         // 4096

// -------------------- device scratch (allocation-free rule) --------------------
__device__ __nv_bfloat16 g_xh[(size_t)MM*DD],  g_xl[(size_t)MM*DD];
__device__ __nv_bfloat16 g_qh[(size_t)MM*DD],  g_ql[(size_t)MM*DD];
__device__ __nv_bfloat16 g_kh[(size_t)MM*KVD], g_kl[(size_t)MM*KVD];
__device__ __nv_bfloat16 g_vh[(size_t)MM*KVD], g_vl[(size_t)MM*KVD];
__device__ __nv_bfloat16 g_ah[(size_t)MM*DD],  g_al[(size_t)MM*DD];
// transposed weights: [N][K] (K contiguous) -> col-major B for mma.row.col
__device__ __nv_bfloat16 g_wqh[(size_t)DD*DD],  g_wql[(size_t)DD*DD];
__device__ __nv_bfloat16 g_wkh[(size_t)KVD*DD], g_wkl[(size_t)KVD*DD];
__device__ __nv_bfloat16 g_wvh[(size_t)KVD*DD], g_wvl[(size_t)KVD*DD];
__device__ __nv_bfloat16 g_woh[(size_t)DD*DD],  g_wol[(size_t)DD*DD];

// -------------------- helpers (plain sm_80+ PTX only) --------------------
__device__ __forceinline__ uint32_t smem_u32(const void* p) {
    uint32_t a;
    asm("{ .reg .u64 t; cvta.to.shared.u64 t, %1; cvt.u32.u64 %0, t; }" : "=r"(a) : "l"(p));
    return a;
}
__device__ __forceinline__ void cp16(uint32_t saddr, const void* g) {
    asm volatile("cp.async.cg.shared.global [%0], [%1], 16;" :: "r"(saddr), "l"(g));
}
#define CP_COMMIT() asm volatile("cp.async.commit_group;" ::: "memory")
#define CP_WAIT0()  asm volatile("cp.async.wait_group 0;" ::: "memory")

__device__ __forceinline__ void ldsm_x4(uint32_t& r0, uint32_t& r1, uint32_t& r2,
                                        uint32_t& r3, uint32_t addr) {
    asm volatile("ldmatrix.sync.aligned.m8n8.x4.shared.b16 {%0,%1,%2,%3}, [%4];"
                 : "=r"(r0), "=r"(r1), "=r"(r2), "=r"(r3) : "r"(addr));
}
__device__ __forceinline__ void ldsm_x4_t(uint32_t& r0, uint32_t& r1, uint32_t& r2,
                                          uint32_t& r3, uint32_t addr) {
    asm volatile("ldmatrix.sync.aligned.m8n8.x4.trans.shared.b16 {%0,%1,%2,%3}, [%4];"
                 : "=r"(r0), "=r"(r1), "=r"(r2), "=r"(r3) : "r"(addr));
}
__device__ __forceinline__ void mma16816(float* c, const uint32_t* a,
                                         uint32_t b0, uint32_t b1) {
    asm volatile("mma.sync.aligned.m16n8k16.row.col.f32.bf16.bf16.f32 "
                 "{%0,%1,%2,%3}, {%4,%5,%6,%7}, {%8,%9}, {%0,%1,%2,%3};"
                 : "+f"(c[0]), "+f"(c[1]), "+f"(c[2]), "+f"(c[3])
                 : "r"(a[0]), "r"(a[1]), "r"(a[2]), "r"(a[3]), "r"(b0), "r"(b1));
}
__device__ __forceinline__ void pack_split(float a, float b, uint32_t& hh, uint32_t& ll) {
    __nv_bfloat16 ha = __float2bfloat16_rn(a), hb = __float2bfloat16_rn(b);
    __nv_bfloat162 H(ha, hb);
    __nv_bfloat162 L(__float2bfloat16_rn(a - __bfloat162float(ha)),
                     __float2bfloat16_rn(b - __bfloat162float(hb)));
    hh = *(uint32_t*)&H;
    ll = *(uint32_t*)&L;
}

// GEMM smem: 128 rows x 32 bf16 (64B rows, 4 chunks), phys chunk = c ^ ((row>>1)&3)
__device__ __forceinline__ uint32_t sw_off(int row, int c) {
    return (uint32_t)(row * 64 + ((c ^ ((row >> 1) & 3)) << 4));
}

// -------------------- prep kernels --------------------
__global__ void split_pair(const float* __restrict__ X, __nv_bfloat16* __restrict__ Xh,
                           __nv_bfloat16* __restrict__ Xl, int n4) {
    int i = blockIdx.x * blockDim.x + threadIdx.x;
    if (i >= n4) return;
    float4 v = ((const float4*)X)[i];
    __nv_bfloat16 h0 = __float2bfloat16_rn(v.x), h1 = __float2bfloat16_rn(v.y);
    __nv_bfloat16 h2 = __float2bfloat16_rn(v.z), h3 = __float2bfloat16_rn(v.w);
    ((__nv_bfloat162*)Xh)[2*i+0] = __nv_bfloat162(h0, h1);
    ((__nv_bfloat162*)Xh)[2*i+1] = __nv_bfloat162(h2, h3);
    ((__nv_bfloat162*)Xl)[2*i+0] = __nv_bfloat162(
        __float2bfloat16_rn(v.x - __bfloat162float(h0)),
        __float2bfloat16_rn(v.y - __bfloat162float(h1)));
    ((__nv_bfloat162*)Xl)[2*i+1] = __nv_bfloat162(
        __float2bfloat16_rn(v.z - __bfloat162float(h2)),
        __float2bfloat16_rn(v.w - __bfloat162float(h3)));
}

__global__ void splitT(const float* __restrict__ W, __nv_bfloat16* __restrict__ Th,
                       __nv_bfloat16* __restrict__ Tl, int K, int N) {
    __shared__ float t[32][33];
    int n0 = blockIdx.x * 32, k0 = blockIdx.y * 32;
    int tx = threadIdx.x, ty = threadIdx.y;
    #pragma unroll
    for (int j = 0; j < 32; j += 8)
        t[ty + j][tx] = W[(size_t)(k0 + ty + j) * N + n0 + tx];
    __syncthreads();
    #pragma unroll
    for (int j = 0; j < 32; j += 8) {
        float v = t[tx][ty + j];
        __nv_bfloat16 h = __float2bfloat16_rn(v);
        size_t o = (size_t)(n0 + ty + j) * K + k0 + tx;
        Th[o] = h;
        Tl[o] = __float2bfloat16_rn(v - __bfloat162float(h));
    }
}

// -------------------- split-bf16 HMMA GEMM --------------------
#define TILE_B 8192
#define BUF_B  (4 * TILE_B)
#define SMEM_GEMM (2 * BUF_B)

template <bool SPLIT>
__global__ __launch_bounds__(256) void gemm_mma(
    const __nv_bfloat16* __restrict__ Ah, const __nv_bfloat16* __restrict__ Al,
    const __nv_bfloat16* __restrict__ Bh, const __nv_bfloat16* __restrict__ Bl,
    float* __restrict__ Cf, __nv_bfloat16* __restrict__ Ch,
    __nv_bfloat16* __restrict__ Cl, int M, int N, int K)
{
    extern __shared__ char sm[];
    uint32_t sb = smem_u32(sm);
    int tid = threadIdx.x, lid = tid & 31, wid = tid >> 5;
    int wm = (wid & 3) * 32;
    int wn = (wid >> 2) * 64;
    int bm0 = blockIdx.y * 128, bn0 = blockIdx.x * 128;

    float c[2][8][4];
    #pragma unroll
    for (int i = 0; i < 2; i++)
        #pragma unroll
        for (int j = 0; j < 8; j++)
            #pragma unroll
            for (int q = 0; q < 4; q++) c[i][j][q] = 0.f;

    int r0_ = tid >> 2, c0_ = tid & 3;
    int r1_ = (tid + 256) >> 2, c1_ = (tid + 256) & 3;
    uint32_t so0 = sw_off(r0_, c0_), so1 = sw_off(r1_, c1_);

    auto issue_load = [&](int buf, int k0) {
        uint32_t base = sb + buf * BUF_B;
        const __nv_bfloat16* a0 = Ah + (size_t)(bm0 + r0_) * K + k0 + c0_ * 8;
        const __nv_bfloat16* a1 = Ah + (size_t)(bm0 + r1_) * K + k0 + c1_ * 8;
        const __nv_bfloat16* b0 = Bh + (size_t)(bn0 + r0_) * K + k0 + c0_ * 8;
        const __nv_bfloat16* b1 = Bh + (size_t)(bn0 + r1_) * K + k0 + c1_ * 8;
        size_t dA = (size_t)(Al - Ah), dB = (size_t)(Bl - Bh);
        cp16(base + 0*TILE_B + so0, a0);      cp16(base + 0*TILE_B + so1, a1);
        cp16(base + 1*TILE_B + so0, a0 + dA); cp16(base + 1*TILE_B + so1, a1 + dA);
        cp16(base + 2*TILE_B + so0, b0);      cp16(base + 2*TILE_B + so1, b1);
        cp16(base + 3*TILE_B + so0, b0 + dB); cp16(base + 3*TILE_B + so1, b1 + dB);
        CP_COMMIT();
    };

    int NK = K / 32;
    issue_load(0, 0);

    for (int kt = 0; kt < NK; kt++) {
        CP_WAIT0();
        __syncthreads();
        if (kt + 1 < NK) issue_load((kt + 1) & 1, (kt + 1) * 32);

        uint32_t base = sb + (kt & 1) * BUF_B;
        #pragma unroll
        for (int ks = 0; ks < 2; ks++) {
            int kc = ks * 2;
            uint32_t ah[2][4], al[2][4], bh[4][4], bl[4][4];
            #pragma unroll
            for (int mt = 0; mt < 2; mt++) {
                int row = wm + mt * 16 + (lid & 15);
                int ch = kc + (lid >> 4);
                uint32_t off = sw_off(row, ch);
                ldsm_x4(ah[mt][0], ah[mt][1], ah[mt][2], ah[mt][3], base + 0*TILE_B + off);
                ldsm_x4(al[mt][0], al[mt][1], al[mt][2], al[mt][3], base + 1*TILE_B + off);
            }
            #pragma unroll
            for (int bt = 0; bt < 4; bt++) {
                int row = wn + bt * 16 + (lid & 7) + ((lid >> 4) << 3);
                int ch = kc + ((lid >> 3) & 1);
                uint32_t off = sw_off(row, ch);
                ldsm_x4(bh[bt][0], bh[bt][1], bh[bt][2], bh[bt][3], base + 2*TILE_B + off);
                ldsm_x4(bl[bt][0], bl[bt][1], bl[bt][2], bl[bt][3], base + 3*TILE_B + off);
            }
            #pragma unroll
            for (int mt = 0; mt < 2; mt++)
                #pragma unroll
                for (int bt = 0; bt < 4; bt++)
                    #pragma unroll
                    for (int hn = 0; hn < 2; hn++) {
                        float* cc = c[mt][bt * 2 + hn];
                        mma16816(cc, ah[mt], bh[bt][hn*2], bh[bt][hn*2+1]);
                        mma16816(cc, ah[mt], bl[bt][hn*2], bl[bt][hn*2+1]);
                        mma16816(cc, al[mt], bh[bt][hn*2], bh[bt][hn*2+1]);
                    }
        }
        __syncthreads();
    }

    #pragma unroll
    for (int mt = 0; mt < 2; mt++) {
        int row = bm0 + wm + mt * 16 + (lid >> 2);
        #pragma unroll
        for (int nt = 0; nt < 8; nt++) {
            int col = bn0 + wn + nt * 8 + (lid & 3) * 2;
            if (SPLIT) {
                uint32_t hh, ll;
                pack_split(c[mt][nt][0], c[mt][nt][1], hh, ll);
                *(uint32_t*)&Ch[(size_t)row * N + col] = hh;
                *(uint32_t*)&Cl[(size_t)row * N + col] = ll;
                pack_split(c[mt][nt][2], c[mt][nt][3], hh, ll);
                *(uint32_t*)&Ch[(size_t)(row + 8) * N + col] = hh;
                *(uint32_t*)&Cl[(size_t)(row + 8) * N + col] = ll;
            } else {
                *(float2*)&Cf[(size_t)row * N + col]       = make_float2(c[mt][nt][0], c[mt][nt][1]);
                *(float2*)&Cf[(size_t)(row + 8) * N + col] = make_float2(c[mt][nt][2], c[mt][nt][3]);
            }
        }
    }
}

// -------------------- HMMA flash attention (split-bf16, causal, GQA) ----------
// 128 threads / 4 warps; 64 q rows per CTA (16 per warp); kv tile 64.
// smem: kv double buffer 2x32KB (kh,kl,vh,vl 8KB each) + Q stage 16KB = 80KB.
#define KBUF 8192
#define SMEM_FLASH (2*32768 + 16384)

__global__ __launch_bounds__(128) void flash_mma(
    const __nv_bfloat16* __restrict__ Qh, const __nv_bfloat16* __restrict__ Ql,
    const __nv_bfloat16* __restrict__ Kh, const __nv_bfloat16* __restrict__ Kl,
    const __nv_bfloat16* __restrict__ Vh, const __nv_bfloat16* __restrict__ Vl,
    __nv_bfloat16* __restrict__ Oh, __nv_bfloat16* __restrict__ Ol)
{
    extern __shared__ char sm[];
    uint32_t sb = smem_u32(sm);
    const int qt = (TT/64 - 1) - blockIdx.x;       // big tiles first
    const int h = blockIdx.y, b = blockIdx.z, g = h >> 2;
    int tid = threadIdx.x, lid = tid & 31, w = tid >> 5;

    const uint32_t qbase = sb + 65536;
    const size_t kvrow0 = (size_t)b * TT;
    const __nv_bfloat16* kvp[4] = {
        Kh + kvrow0 * KVD + g * HDIM, Kl + kvrow0 * KVD + g * HDIM,
        Vh + kvrow0 * KVD + g * HDIM, Vl + kvrow0 * KVD + g * HDIM };

    // per-thread cp.async slots: per 8KB tile, 512 chunks / 128 thr = 4 each
    int prow[4], pc[4];
    uint32_t pso[4];
    #pragma unroll
    for (int i = 0; i < 4; i++) {
        int idx = tid + i * 128;
        prow[i] = idx >> 3; pc[i] = idx & 7;
        pso[i] = (uint32_t)(prow[i] * 128 + ((pc[i] ^ (prow[i] & 7)) << 4));
    }
    auto prefetch = [&](int buf, int kt) {
        uint32_t base = sb + buf * 32768;
        int kv0 = kt * 64;
        #pragma unroll
        for (int p = 0; p < 4; p++)
            #pragma unroll
            for (int i = 0; i < 4; i++)
                cp16(base + p * KBUF + pso[i],
                     kvp[p] + (size_t)(kv0 + prow[i]) * KVD + pc[i] * 8);
        CP_COMMIT();
    };

    prefetch(0, 0);

    // ---- stage Q tile (h+l) and extract fragments ----
    {
        const size_t q0 = ((size_t)b * TT + qt * 64);
        #pragma unroll
        for (int i = 0; i < 4; i++) {
            const uint4 vh4 = *(const uint4*)(Qh + (q0 + prow[i]) * DD + h * HDIM + pc[i] * 8);
            const uint4 vl4 = *(const uint4*)(Ql + (q0 + prow[i]) * DD + h * HDIM + pc[i] * 8);
            *(uint4*)(sm + 65536 + pso[i]) = vh4;
            *(uint4*)(sm + 65536 + 8192 + pso[i]) = vl4;
        }
    }
    __syncthreads();

    uint32_t qhf[4][4], qlf[4][4];
    {
        int row = w * 16 + (lid & 15);
        #pragma unroll
        for (int kc = 0; kc < 4; kc++) {
            int ch = 2 * kc + (lid >> 4);
            uint32_t off = (uint32_t)(row * 128 + ((ch ^ (row & 7)) << 4));
            ldsm_x4(qhf[kc][0], qhf[kc][1], qhf[kc][2], qhf[kc][3], qbase + off);
            ldsm_x4(qlf[kc][0], qlf[kc][1], qlf[kc][2], qlf[kc][3], qbase + 8192 + off);
        }
    }

    // precomputed ldmatrix offsets
    uint32_t soff_s[4], voff[4];
    #pragma unroll
    for (int kc = 0; kc < 4; kc++)
        soff_s[kc] = (uint32_t)((lid & 15) * 128 + (((2*kc + (lid >> 4)) ^ (lid & 7)) << 4));
    #pragma unroll
    for (int hg = 0; hg < 4; hg++)
        voff[hg] = (uint32_t)(((lid & 7) + (((lid >> 3) & 1) << 3)) * 128 +
                              (((2*hg + (lid >> 4)) ^ (lid & 7)) << 4));

    float o[8][4];
    #pragma unroll
    for (int nt = 0; nt < 8; nt++)
        #pragma unroll
        for (int i = 0; i < 4; i++) o[nt][i] = 0.f;
    float mrow[2] = {-1e30f, -1e30f}, lrow[2] = {0.f, 0.f};

    for (int kt = 0; kt <= qt; kt++) {
        CP_WAIT0();
        __syncthreads();
        if (kt < qt) prefetch((kt + 1) & 1, kt + 1);

        uint32_t base = sb + (kt & 1) * 32768;

        // ---- S = Q K^T (3 split passes fused) ----
        float s[8][4];
        #pragma unroll
        for (int nt = 0; nt < 8; nt++)
            #pragma unroll
            for (int i = 0; i < 4; i++) s[nt][i] = 0.f;

        #pragma unroll
        for (int kc = 0; kc < 4; kc++) {
            #pragma unroll
            for (int tp = 0; tp < 4; tp++) {
                uint32_t kh0, kh1, kh2, kh3, kl0, kl1, kl2, kl3;
                uint32_t off = soff_s[kc] + tp * 2048;
                ldsm_x4(kh0, kh1, kh2, kh3, base + 0*KBUF + off);
                ldsm_x4(kl0, kl1, kl2, kl3, base + 1*KBUF + off);
                float* s0 = s[2*tp];
                float* s1 = s[2*tp+1];
                mma16816(s0, qhf[kc], kh0, kh2);
                mma16816(s0, qhf[kc], kl0, kl2);
                mma16816(s0, qlf[kc], kh0, kh2);
                mma16816(s1, qhf[kc], kh1, kh3);
                mma16816(s1, qhf[kc], kl1, kl3);
                mma16816(s1, qlf[kc], kh1, kh3);
            }
        }

        // ---- scale + causal mask ----
        #pragma unroll
        for (int nt = 0; nt < 8; nt++)
            #pragma unroll
            for (int i = 0; i < 4; i++) s[nt][i] *= 0.125f;
        if (kt == qt) {
            #pragma unroll
            for (int nt = 0; nt < 8; nt++)
                #pragma unroll
                for (int i = 0; i < 4; i++) {
                    int col = nt * 8 + 2 * (lid & 3) + (i & 1);
                    int r = w * 16 + (lid >> 2) + 8 * (i >> 1);
                    if (col > r) s[nt][i] = -1e30f;
                }
        }

        // ---- online softmax ----
        float mx0 = mrow[0], mx1 = mrow[1];
        #pragma unroll
        for (int nt = 0; nt < 8; nt++) {
            mx0 = fmaxf(mx0, fmaxf(s[nt][0], s[nt][1]));
            mx1 = fmaxf(mx1, fmaxf(s[nt][2], s[nt][3]));
        }
        mx0 = fmaxf(mx0, __shfl_xor_sync(0xffffffff, mx0, 1));
        mx0 = fmaxf(mx0, __shfl_xor_sync(0xffffffff, mx0, 2));
        mx1 = fmaxf(mx1, __shfl_xor_sync(0xffffffff, mx1, 1));
        mx1 = fmaxf(mx1, __shfl_xor_sync(0xffffffff, mx1, 2));
        float corr0 = __expf(mrow[0] - mx0);
        float corr1 = __expf(mrow[1] - mx1);
        mrow[0] = mx0; mrow[1] = mx1;

        float ps0 = 0.f, ps1 = 0.f;
        #pragma unroll
        for (int nt = 0; nt < 8; nt++) {
            float p0 = __expf(s[nt][0] - mx0); s[nt][0] = p0; ps0 += p0;
            float p1 = __expf(s[nt][1] - mx0); s[nt][1] = p1; ps0 += p1;
            float p2 = __expf(s[nt][2] - mx1); s[nt][2] = p2; ps1 += p2;
            float p3 = __expf(s[nt][3] - mx1); s[nt][3] = p3; ps1 += p3;
        }
        ps0 += __shfl_xor_sync(0xffffffff, ps0, 1);
        ps0 += __shfl_xor_sync(0xffffffff, ps0, 2);
        ps1 += __shfl_xor_sync(0xffffffff, ps1, 1);
        ps1 += __shfl_xor_sync(0xffffffff, ps1, 2);
        lrow[0] = lrow[0] * corr0 + ps0;
        lrow[1] = lrow[1] * corr1 + ps1;

        #pragma unroll
        for (int nt = 0; nt < 8; nt++) {
            o[nt][0] *= corr0; o[nt][1] *= corr0;
            o[nt][2] *= corr1; o[nt][3] *= corr1;
        }

        // ---- O += P V (3 split passes fused) ----
        #pragma unroll
        for (int kc = 0; kc < 4; kc++) {
            uint32_t afh[4], afl[4];
            pack_split(s[2*kc][0],   s[2*kc][1],   afh[0], afl[0]);
            pack_split(s[2*kc][2],   s[2*kc][3],   afh[1], afl[1]);
            pack_split(s[2*kc+1][0], s[2*kc+1][1], afh[2], afl[2]);
            pack_split(s[2*kc+1][2], s[2*kc+1][3], afh[3], afl[3]);
            #pragma unroll
            for (int hg = 0; hg < 4; hg++) {
                uint32_t vh0, vh1, vh2, vh3, vl0, vl1, vl2, vl3;
                uint32_t off = voff[hg] + kc * 2048;
                ldsm_x4_t(vh0, vh1, vh2, vh3, base + 2*KBUF + off);
                ldsm_x4_t(vl0, vl1, vl2, vl3, base + 3*KBUF + off);
                float* o0 = o[2*hg];
                float* o1 = o[2*hg+1];
                mma16816(o0, afh, vh0, vh1);
                mma16816(o0, afl, vh0, vh1);
                mma16816(o0, afh, vl0, vl1);
                mma16816(o1, afh, vh2, vh3);
                mma16816(o1, afl, vh2, vh3);
                mma16816(o1, afh, vl2, vl3);
            }
        }
        __syncthreads();
    }

    // ---- finalize: normalize, split to bf16, store ----
    float inv0 = 1.f / lrow[0], inv1 = 1.f / lrow[1];
    size_t r0g = (size_t)b * TT + qt * 64 + w * 16 + (lid >> 2);
    #pragma unroll
    for (int nt = 0; nt < 8; nt++) {
        int col = h * HDIM + nt * 8 + 2 * (lid & 3);
        uint32_t hh, ll;
        pack_split(o[nt][0] * inv0, o[nt][1] * inv0, hh, ll);
        *(uint32_t*)&Oh[r0g * DD + col] = hh;
        *(uint32_t*)&Ol[r0g * DD + col] = ll;
        pack_split(o[nt][2] * inv1, o[nt][3] * inv1, hh, ll);
        *(uint32_t*)&Oh[(r0g + 8) * DD + col] = hh;
        *(uint32_t*)&Ol[(r0g + 8) * DD + col] = ll;
    }
}

// -------------------- launch --------------------
extern "C" void kernel_launch(void* const* d_in, const int* in_sizes, int n_in,
                              void* d_out, int out_size)
{
    const float* x  = (const float*)d_in[0];
    const float* Wq = (const float*)d_in[1];
    const float* Wk = (const float*)d_in[2];
    const float* Wv = (const float*)d_in[3];
    const float* Wo = (const float*)d_in[4];
    float* out = (float*)d_out;

    __nv_bfloat16 *xh, *xl, *qh, *ql, *kh, *kl, *vh, *vl, *ah, *al;
    __nv_bfloat16 *wqh, *wql, *wkh, *wkl, *wvh, *wvl, *woh, *wol;
    cudaGetSymbolAddress((void**)&xh, g_xh);   cudaGetSymbolAddress((void**)&xl, g_xl);
    cudaGetSymbolAddress((void**)&qh, g_qh);   cudaGetSymbolAddress((void**)&ql, g_ql);
    cudaGetSymbolAddress((void**)&kh, g_kh);   cudaGetSymbolAddress((void**)&kl, g_kl);
    cudaGetSymbolAddress((void**)&vh, g_vh);   cudaGetSymbolAddress((void**)&vl, g_vl);
    cudaGetSymbolAddress((void**)&ah, g_ah);   cudaGetSymbolAddress((void**)&al, g_al);
    cudaGetSymbolAddress((void**)&wqh, g_wqh); cudaGetSymbolAddress((void**)&wql, g_wql);
    cudaGetSymbolAddress((void**)&wkh, g_wkh); cudaGetSymbolAddress((void**)&wkl, g_wkl);
    cudaGetSymbolAddress((void**)&wvh, g_wvh); cudaGetSymbolAddress((void**)&wvl, g_wvl);
    cudaGetSymbolAddress((void**)&woh, g_woh); cudaGetSymbolAddress((void**)&wol, g_wol);

    cudaFuncSetAttribute(gemm_mma<true>,  cudaFuncAttributeMaxDynamicSharedMemorySize, SMEM_GEMM);
    cudaFuncSetAttribute(gemm_mma<false>, cudaFuncAttributeMaxDynamicSharedMemorySize, SMEM_GEMM);
    cudaFuncSetAttribute(flash_mma, cudaFuncAttributeMaxDynamicSharedMemorySize, SMEM_FLASH);

    // prep
    int n4 = MM * DD / 4;
    split_pair<<<(n4 + 255) / 256, 256>>>(x, xh, xl, n4);
    splitT<<<dim3(DD / 32,  DD / 32), dim3(32, 8)>>>(Wq, wqh, wql, DD, DD);
    splitT<<<dim3(KVD / 32, DD / 32), dim3(32, 8)>>>(Wk, wkh, wkl, DD, KVD);
    splitT<<<dim3(KVD / 32, DD / 32), dim3(32, 8)>>>(Wv, wvh, wvl, DD, KVD);
    splitT<<<dim3(DD / 32,  DD / 32), dim3(32, 8)>>>(Wo, woh, wol, DD, DD);

    // projections -> split bf16 outputs
    gemm_mma<true><<<dim3(DD / 128,  MM / 128), 256, SMEM_GEMM>>>(
        xh, xl, wqh, wql, nullptr, qh, ql, MM, DD,  DD);
    gemm_mma<true><<<dim3(KVD / 128, MM / 128), 256, SMEM_GEMM>>>(
        xh, xl, wkh, wkl, nullptr, kh, kl, MM, KVD, DD);
    gemm_mma<true><<<dim3(KVD / 128, MM / 128), 256, SMEM_GEMM>>>(
        xh, xl, wvh, wvl, nullptr, vh, vl, MM, KVD, DD);

    // attention (HMMA) -> split bf16 output
    flash_mma<<<dim3(TT / 64, HH, BB), 128, SMEM_FLASH>>>(
        qh, ql, kh, kl, vh, vl, ah, al);

    // output projection -> fp32
    gemm_mma<false><<<dim3(DD / 128, MM / 128), 256, SMEM_GEMM>>>(
        ah, al, woh, wol, out, nullptr, nullptr, MM, DD, DD);
}